// round 6
// baseline (speedup 1.0000x reference)
#include <cuda_runtime.h>
#include <math.h>

// Problem constants
#define B   256
#define D   512
#define KB  8         // number of block-diagonal blocks
#define M   64        // dictionary size
#define N   64        // block dim
#define NN  4096      // N*N
#define FISTA_ITERS 20
#define FISTA_LR    0.01f
#define LAMBDA_PRIOR 0.05f
#define SOFT_THR    (FISTA_LR * LAMBDA_PRIOR)
#define LFWD 14       // forward Taylor terms (q_l, l<=LFWD)
#define JG   11       // gradient pair cutoff: i+l <= JG
#define GCH  32       // split-K chunks for the gradient GEMM

// ---------------- scratch (static device globals; no allocation) -----------
__device__ float g_T[B * KB * NN];      // 32 MB: T[b,k,u,v]
__device__ float g_dLdT[B * KB * NN];   // 32 MB
__device__ float g_c[B * M];
__device__ float g_y[B * M];
__device__ float g_part[GCH * B * M];   // 2 MB partial gradients

__constant__ float c_invf[16] = {
    1.0f, 1.0f, 0.5f,
    1.6666666666666666e-1f, 4.1666666666666664e-2f, 8.3333333333333332e-3f,
    1.3888888888888889e-3f, 1.9841269841269841e-4f, 2.4801587301587302e-5f,
    2.7557319223985893e-6f, 2.7557319223985888e-7f, 2.5052108385441720e-8f,
    2.0876756987868100e-9f, 1.6059043836821613e-10f, 1.1470745597729725e-11f,
    7.6471637318198164e-13f};

// ---------------- init: zero c and y ---------------------------------------
__global__ void init_kernel() {
    int i = blockIdx.x * blockDim.x + threadIdx.x;
    if (i < B * M) { g_c[i] = 0.0f; g_y[i] = 0.0f; }
}

// ---------------- T = coef @ psi  (per k: [B,M] @ [M,NN]) -------------------
// grid (64 col-tiles, 4 b-tiles, KB), block (16,16). 64x64 output tile, K-dim=64.
__global__ void gemm_T_kernel(const float* __restrict__ psi, int use_c) {
    const float* __restrict__ coef = use_c ? g_c : g_y;
    int ct = blockIdx.x;          // column tile (of NN)
    int bt = blockIdx.y;          // batch tile
    int k  = blockIdx.z;

    __shared__ float Ys[64][68];  // [b][m]   (68: float4-aligned row stride)
    __shared__ float Ps[64][68];  // [m][col]

    int tx = threadIdx.x, ty = threadIdx.y;
    int tid = ty * 16 + tx;
    int col0 = ct * 64;

#pragma unroll
    for (int it = 0; it < 16; ++it) {
        int idx = it * 256 + tid;
        int r = idx >> 6, c = idx & 63;
        Ys[r][c] = coef[(bt * 64 + r) * M + c];
        Ps[r][c] = psi[(k * M + r) * NN + col0 + c];
    }
    __syncthreads();

    float acc[4][4] = {{0.f}};
#pragma unroll 16
    for (int m = 0; m < 64; ++m) {
        float a0 = Ys[ty * 4 + 0][m];
        float a1 = Ys[ty * 4 + 1][m];
        float a2 = Ys[ty * 4 + 2][m];
        float a3 = Ys[ty * 4 + 3][m];
        float4 bv = *(const float4*)&Ps[m][tx * 4];
        acc[0][0] += a0 * bv.x; acc[0][1] += a0 * bv.y; acc[0][2] += a0 * bv.z; acc[0][3] += a0 * bv.w;
        acc[1][0] += a1 * bv.x; acc[1][1] += a1 * bv.y; acc[1][2] += a1 * bv.z; acc[1][3] += a1 * bv.w;
        acc[2][0] += a2 * bv.x; acc[2][1] += a2 * bv.y; acc[2][2] += a2 * bv.z; acc[2][3] += a2 * bv.w;
        acc[3][0] += a3 * bv.x; acc[3][1] += a3 * bv.y; acc[3][2] += a3 * bv.z; acc[3][3] += a3 * bv.w;
    }

#pragma unroll
    for (int i = 0; i < 4; ++i) {
        int b = bt * 64 + ty * 4 + i;
        float4 o = make_float4(acc[i][0], acc[i][1], acc[i][2], acc[i][3]);
        *(float4*)&g_T[(b * KB + k) * NN + col0 + tx * 4] = o;
    }
}

// ---------------- per-(b,k): forward series + rank-1 expm VJP ---------------
// q_l = T^l z0 ; Texp z0 = sum q_l/l! ; r = Texp z0 - z1 ; p_i = (T^T)^i r
// dL/dT[u,v] = sum_{i+l<=JG} p_i[u] q_l[v] / (i+l+1)!  =  sum_i p_i[u] w_i[v]
__global__ void expm_grad_kernel(const float* __restrict__ z0g,
                                 const float* __restrict__ z1g) {
    int bk = blockIdx.x;              // = b*KB + k
    int b = bk >> 3, k = bk & 7;
    int t = threadIdx.x;              // 0..63

    __shared__ float Ts[64][65];
    __shared__ float qs[LFWD + 1][64];
    __shared__ float ps[JG + 1][64];

    const float* __restrict__ Tg = g_T + (size_t)bk * NN;
#pragma unroll 8
    for (int i = 0; i < 64; ++i) Ts[i][t] = Tg[i * 64 + t];

    float z0v = z0g[b * D + k * N + t];
    qs[0][t] = z0v;
    __syncthreads();

    // forward: q_l and accumulated expm(T) z0
    float fwd = z0v;
    for (int l = 1; l <= LFWD; ++l) {
        float s = 0.f;
#pragma unroll 16
        for (int v = 0; v < 64; ++v) s += Ts[t][v] * qs[l - 1][v];
        qs[l][t] = s;
        fwd += c_invf[l] * s;
        __syncthreads();
    }

    float r = fwd - z1g[b * D + k * N + t];
    ps[0][t] = r;
    __syncthreads();

    // p_i = (T^T)^i r
    for (int i = 1; i <= JG; ++i) {
        float s = 0.f;
#pragma unroll 16
        for (int w = 0; w < 64; ++w) s += Ts[w][t] * ps[i - 1][w];
        ps[i][t] = s;
        __syncthreads();
    }

    // thread t owns column v=t:  w_i = sum_{l<=JG-i} invf[i+l+1] q_l[t]
    float ql[JG + 1];
#pragma unroll
    for (int l = 0; l <= JG; ++l) ql[l] = qs[l][t];
    float wv[JG + 1];
#pragma unroll
    for (int i = 0; i <= JG; ++i) {
        float s = 0.f;
#pragma unroll
        for (int l = 0; l <= JG; ++l)
            if (i + l <= JG) s += c_invf[i + l + 1] * ql[l];
        wv[i] = s;
    }

    float* __restrict__ outg = g_dLdT + (size_t)bk * NN;
#pragma unroll 4
    for (int u = 0; u < 64; ++u) {
        float s = 0.f;
#pragma unroll
        for (int i = 0; i <= JG; ++i) s += ps[i][u] * wv[i];
        outg[u * 64 + t] = s;   // coalesced: thread t writes column t of row u
    }
}

// ---------------- g[b,m] = sum_{k,uv} dLdT[b,k,uv] psi[k,m,uv]  (split-K) ---
// grid (GCH chunks, 8 b-tiles of 32), block 256.
__global__ void gemm_g_kernel(const float* __restrict__ psi) {
    int cc = blockIdx.x;              // chunk: k = cc/4, uv window = (cc&3)*1024
    int bt = blockIdx.y;
    int k = cc >> 2;
    int uv0 = (cc & 3) * 1024;

    __shared__ float As[32][65];      // [b_local][j]
    __shared__ float Pm[64][65];      // [m][j]

    int tid = threadIdx.x;
    int tm = tid & 63;                // m
    int tb = tid >> 6;                // 0..3 -> rows tb*8..tb*8+7
    float acc[8] = {0.f};

    for (int step = 0; step < 16; ++step) {
        int j0 = uv0 + step * 64;
#pragma unroll
        for (int it = 0; it < 8; ++it) {
            int idx = it * 256 + tid;
            int r = idx >> 6, c = idx & 63;
            As[r][c] = g_dLdT[((size_t)(bt * 32 + r) * KB + k) * NN + j0 + c];
        }
#pragma unroll
        for (int it = 0; it < 16; ++it) {
            int idx = it * 256 + tid;
            int r = idx >> 6, c = idx & 63;
            Pm[r][c] = psi[(k * M + r) * NN + j0 + c];
        }
        __syncthreads();
#pragma unroll 8
        for (int j = 0; j < 64; ++j) {
            float p = Pm[tm][j];
#pragma unroll
            for (int i = 0; i < 8; ++i) acc[i] += As[tb * 8 + i][j] * p;
        }
        __syncthreads();
    }

#pragma unroll
    for (int i = 0; i < 8; ++i)
        g_part[((size_t)cc * B + bt * 32 + tb * 8 + i) * M + tm] = acc[i];
}

// ---------------- FISTA update: reduce partials, prox, momentum ------------
__global__ void fista_update_kernel(float mom) {
    int i = blockIdx.x * blockDim.x + threadIdx.x;
    if (i >= B * M) return;
    float s = 0.f;
#pragma unroll
    for (int cc = 0; cc < GCH; ++cc) s += g_part[cc * (B * M) + i];
    float yv = g_y[i], cold = g_c[i];
    float x = yv - FISTA_LR * s;
    float ax = fabsf(x) - SOFT_THR;
    float cnew = (ax > 0.f) ? copysignf(ax, x) : 0.f;
    g_c[i] = cnew;
    g_y[i] = cnew + mom * (cnew - cold);
}

// ---------------- final forward: out = expm(T(c)) z0 ------------------------
__global__ void final_fwd_kernel(const float* __restrict__ z0g,
                                 float* __restrict__ out) {
    int bk = blockIdx.x;
    int b = bk >> 3, k = bk & 7;
    int t = threadIdx.x;

    __shared__ float Ts[64][65];
    __shared__ float w[64];

    const float* __restrict__ Tg = g_T + (size_t)bk * NN;
#pragma unroll 8
    for (int i = 0; i < 64; ++i) Ts[i][t] = Tg[i * 64 + t];
    float z = z0g[b * D + k * N + t];
    w[t] = z;
    __syncthreads();

    float acc = z;
    for (int l = 1; l <= LFWD; ++l) {
        float s = 0.f;
#pragma unroll 16
        for (int v = 0; v < 64; ++v) s += Ts[t][v] * w[v];
        __syncthreads();
        w[t] = s;
        acc += c_invf[l] * s;
        __syncthreads();
    }
    out[b * D + k * N + t] = acc;
}

// ---------------- host driver ----------------------------------------------
extern "C" void kernel_launch(void* const* d_in, const int* in_sizes, int n_in,
                              void* d_out, int out_size) {
    const float* z0  = (const float*)d_in[0];   // feature_0 [B, D]
    const float* z1  = (const float*)d_in[1];   // feature_1 [B, D]
    const float* psi = (const float*)d_in[2];   // psi [K, M, N, N]
    float* out = (float*)d_out;                 // [B, D] fp32

    init_kernel<<<(B * M + 255) / 256, 256>>>();

    float t = 1.0f;
    for (int it = 0; it < FISTA_ITERS; ++it) {
        gemm_T_kernel<<<dim3(64, 4, KB), dim3(16, 16)>>>(psi, 0);
        expm_grad_kernel<<<B * KB, 64>>>(z0, z1);
        gemm_g_kernel<<<dim3(GCH, 8), 256>>>(psi);
        float tn = 0.5f * (1.0f + sqrtf(1.0f + 4.0f * t * t));
        float mom = (t - 1.0f) / tn;
        t = tn;
        fista_update_kernel<<<(B * M + 255) / 256, 256>>>(mom);
    }

    gemm_T_kernel<<<dim3(64, 4, KB), dim3(16, 16)>>>(psi, 1);
    final_fwd_kernel<<<B * KB, 64>>>(z0, out);
}

// round 7
// speedup vs baseline: 1.4455x; 1.4455x over previous
#include <cuda_runtime.h>
#include <math.h>

// Problem constants
#define B   256
#define D   512
#define KB  8         // number of block-diagonal blocks
#define M   64        // dictionary size
#define N   64        // block dim
#define NN  4096      // N*N
#define FISTA_ITERS 20
#define FISTA_LR    0.01f
#define LAMBDA_PRIOR 0.05f
#define SOFT_THR    (FISTA_LR * LAMBDA_PRIOR)
#define LFI 9         // forward Taylor terms inside FISTA loop
#define JGR 7         // gradient pair cutoff: i+l <= JGR
#define LFF 12        // final forward Taylor terms
#define GCH 64        // split-K chunks for the gradient GEMM

#define SMEM_T_BYTES (2 * 64 * 132 * 4)   // 67584 dynamic smem for gemm_T

// ---------------- scratch (static device globals; no allocation) -----------
__device__ float g_T[B * KB * NN];      // 32 MB
__device__ float g_dLdT[B * KB * NN];   // 32 MB
__device__ float g_c[B * M];
__device__ float g_y[B * M];
__device__ float g_part[GCH * B * M];   // 4 MB partial gradients

__constant__ float c_invf[16] = {
    1.0f, 1.0f, 0.5f,
    1.6666666666666666e-1f, 4.1666666666666664e-2f, 8.3333333333333332e-3f,
    1.3888888888888889e-3f, 1.9841269841269841e-4f, 2.4801587301587302e-5f,
    2.7557319223985893e-6f, 2.7557319223985888e-7f, 2.5052108385441720e-8f,
    2.0876756987868100e-9f, 1.6059043836821613e-10f, 1.1470745597729725e-11f,
    7.6471637318198164e-13f};

// ---------------- init: zero c and y ---------------------------------------
__global__ void init_kernel() {
    int i = blockIdx.x * blockDim.x + threadIdx.x;
    if (i < B * M) { g_c[i] = 0.0f; g_y[i] = 0.0f; }
}

// ---------------- T = coef @ psi  (per k: [B,M] @ [M,NN]) -------------------
// 128x128 output tile, K=64 (single stage). 256 threads, 8x8 per thread.
// grid (NN/128=32, B/128=2, KB).
__global__ void __launch_bounds__(256) gemm_T_kernel(const float* __restrict__ psi,
                                                     int use_c) {
    const float* __restrict__ coef = use_c ? g_c : g_y;
    extern __shared__ float sm[];
    float (*Ys)[132] = (float(*)[132])sm;              // [m][b] transposed
    float (*Ps)[132] = (float(*)[132])(sm + 64 * 132); // [m][col]

    int ct = blockIdx.x, bt = blockIdx.y, k = blockIdx.z;
    int tid = threadIdx.x;
    int tx = tid & 15, ty = tid >> 4;
    int col0 = ct * 128, b0 = bt * 128;

    // load Y tile 128b x 64m (transposed into smem)
#pragma unroll
    for (int it = 0; it < 32; ++it) {
        int idx = it * 256 + tid;
        int m = idx & 63, b = idx >> 6;
        Ys[m][b] = coef[(b0 + b) * M + m];
    }
    // load psi tile 64m x 128c (float4)
#pragma unroll
    for (int it = 0; it < 8; ++it) {
        int idx = it * 256 + tid;        // 2048 float4
        int c4 = idx & 31, m = idx >> 5;
        float4 v = *(const float4*)&psi[((size_t)k * M + m) * NN + col0 + c4 * 4];
        *(float4*)&Ps[m][c4 * 4] = v;
    }
    __syncthreads();

    float acc[8][8];
#pragma unroll
    for (int i = 0; i < 8; ++i)
#pragma unroll
        for (int j = 0; j < 8; ++j) acc[i][j] = 0.f;

#pragma unroll 4
    for (int m = 0; m < 64; ++m) {
        float4 a0 = *(const float4*)&Ys[m][ty * 4];
        float4 a1 = *(const float4*)&Ys[m][64 + ty * 4];
        float4 p0 = *(const float4*)&Ps[m][tx * 4];
        float4 p1 = *(const float4*)&Ps[m][64 + tx * 4];
        float av[8] = {a0.x, a0.y, a0.z, a0.w, a1.x, a1.y, a1.z, a1.w};
        float pv[8] = {p0.x, p0.y, p0.z, p0.w, p1.x, p1.y, p1.z, p1.w};
#pragma unroll
        for (int i = 0; i < 8; ++i)
#pragma unroll
            for (int j = 0; j < 8; ++j) acc[i][j] += av[i] * pv[j];
    }

#pragma unroll
    for (int i = 0; i < 8; ++i) {
        int b = b0 + ((i < 4) ? (ty * 4 + i) : (64 + ty * 4 + i - 4));
        float* orow = &g_T[((size_t)b * KB + k) * NN + col0];
        *(float4*)&orow[tx * 4] =
            make_float4(acc[i][0], acc[i][1], acc[i][2], acc[i][3]);
        *(float4*)&orow[64 + tx * 4] =
            make_float4(acc[i][4], acc[i][5], acc[i][6], acc[i][7]);
    }
}

// ---------------- per-(b,k): forward series + rank-factored expm VJP --------
// q_l = T^l z0 ; fwd = sum q_l/l! ; r = fwd - z1 ; p_i = (T^T)^i r
// dL/dT[u,v] = sum_i p_i[u] * w_i[v],  w_i = sum_{l<=JGR-i} invf[i+l+1] q_l
// T row and column kept in registers; smem only for vector exchange.
__global__ void __launch_bounds__(64) expm_grad_kernel(const float* __restrict__ z0g,
                                                       const float* __restrict__ z1g) {
    int bk = blockIdx.x, b = bk >> 3, k = bk & 7, t = threadIdx.x;
    __shared__ float Ts[64][65];
    __shared__ float qs[LFI + 1][64];
    __shared__ float pex[2][64];
    __shared__ float pst[64][8];

    const float* __restrict__ Tg = g_T + (size_t)bk * NN;
#pragma unroll
    for (int i = 0; i < 64; ++i) Ts[i][t] = Tg[i * 64 + t];
    __syncthreads();

    float Trow[64], Tcol[64];
#pragma unroll
    for (int v = 0; v < 64; ++v) Trow[v] = Ts[t][v];
#pragma unroll
    for (int w = 0; w < 64; ++w) Tcol[w] = Ts[w][t];

    float z0v = z0g[b * D + k * N + t];
    qs[0][t] = z0v;
    __syncthreads();

    float ql[JGR + 1];
    ql[0] = z0v;
    float fwd = z0v;
#pragma unroll
    for (int l = 1; l <= LFI; ++l) {
        float s0 = 0.f, s1 = 0.f, s2 = 0.f, s3 = 0.f;
        const float4* qp = (const float4*)qs[l - 1];
#pragma unroll
        for (int v = 0; v < 16; ++v) {
            float4 q4 = qp[v];
            s0 += Trow[4 * v + 0] * q4.x;
            s1 += Trow[4 * v + 1] * q4.y;
            s2 += Trow[4 * v + 2] * q4.z;
            s3 += Trow[4 * v + 3] * q4.w;
        }
        float s = (s0 + s1) + (s2 + s3);
        qs[l][t] = s;
        if (l <= JGR) ql[l] = s;
        fwd += c_invf[l] * s;
        __syncthreads();
    }

    float r = fwd - z1g[b * D + k * N + t];
    pex[0][t] = r;
    pst[t][0] = r;
    __syncthreads();
#pragma unroll
    for (int i = 1; i <= JGR; ++i) {
        float s0 = 0.f, s1 = 0.f, s2 = 0.f, s3 = 0.f;
        const float4* pp = (const float4*)pex[(i - 1) & 1];
#pragma unroll
        for (int w = 0; w < 16; ++w) {
            float4 p4 = pp[w];
            s0 += Tcol[4 * w + 0] * p4.x;
            s1 += Tcol[4 * w + 1] * p4.y;
            s2 += Tcol[4 * w + 2] * p4.z;
            s3 += Tcol[4 * w + 3] * p4.w;
        }
        float s = (s0 + s1) + (s2 + s3);
        pex[i & 1][t] = s;
        pst[t][i] = s;
        __syncthreads();
    }

    // w_i (thread t owns column v = t)
    float wv[JGR + 1];
#pragma unroll
    for (int i = 0; i <= JGR; ++i) {
        float s = 0.f;
#pragma unroll
        for (int l = 0; l + i <= JGR; ++l) s += c_invf[i + l + 1] * ql[l];
        wv[i] = s;
    }

    float* __restrict__ outg = g_dLdT + (size_t)bk * NN;
#pragma unroll 4
    for (int u = 0; u < 64; ++u) {
        float4 pa = *(const float4*)&pst[u][0];
        float4 pb = *(const float4*)&pst[u][4];
        float s = pa.x * wv[0] + pa.y * wv[1] + pa.z * wv[2] + pa.w * wv[3]
                + pb.x * wv[4] + pb.y * wv[5] + pb.z * wv[6] + pb.w * wv[7];
        outg[u * 64 + t] = s;
    }
}

// ---------------- g[b,m] = sum_{k,uv} dLdT[b,k,uv] psi[k,m,uv]  (split-K) ---
// grid (GCH=64 chunks, 4 b-tiles), 128 threads, output tile 64b x 64m,
// chunk length 512, 8x4 per thread, transposed smem staging.
__global__ void __launch_bounds__(128) gemm_g_kernel(const float* __restrict__ psi) {
    int cc = blockIdx.x;           // chunk: k = cc/8, uv window (cc&7)*512
    int bt = blockIdx.y;
    int k = cc >> 3;
    int uv0 = (cc & 7) * 512;
    int b0 = bt * 64;
    int tid = threadIdx.x;
    int tx = tid & 15, ty = tid >> 4;   // tx: m group, ty in [0,8): b group

    __shared__ float As[64][68];   // [j][b]
    __shared__ float Pm[64][68];   // [j][m]

    float acc[8][4];
#pragma unroll
    for (int i = 0; i < 8; ++i)
#pragma unroll
        for (int j = 0; j < 4; ++j) acc[i][j] = 0.f;

    for (int step = 0; step < 8; ++step) {
        int j0 = uv0 + step * 64;
#pragma unroll
        for (int it = 0; it < 8; ++it) {
            int idx = it * 128 + tid;      // 1024 float4
            int j4 = idx & 15, rb = idx >> 4;
            float4 v = *(const float4*)
                &g_dLdT[((size_t)(b0 + rb) * KB + k) * NN + j0 + j4 * 4];
            As[j4 * 4 + 0][rb] = v.x;
            As[j4 * 4 + 1][rb] = v.y;
            As[j4 * 4 + 2][rb] = v.z;
            As[j4 * 4 + 3][rb] = v.w;
        }
#pragma unroll
        for (int it = 0; it < 8; ++it) {
            int idx = it * 128 + tid;
            int j4 = idx & 15, rm = idx >> 4;
            float4 v = *(const float4*)
                &psi[((size_t)k * M + rm) * NN + j0 + j4 * 4];
            Pm[j4 * 4 + 0][rm] = v.x;
            Pm[j4 * 4 + 1][rm] = v.y;
            Pm[j4 * 4 + 2][rm] = v.z;
            Pm[j4 * 4 + 3][rm] = v.w;
        }
        __syncthreads();
#pragma unroll 4
        for (int j = 0; j < 64; ++j) {
            float4 a0 = *(const float4*)&As[j][ty * 4];
            float4 a1 = *(const float4*)&As[j][32 + ty * 4];
            float4 p0 = *(const float4*)&Pm[j][tx * 4];
            float av[8] = {a0.x, a0.y, a0.z, a0.w, a1.x, a1.y, a1.z, a1.w};
            float pv[4] = {p0.x, p0.y, p0.z, p0.w};
#pragma unroll
            for (int i = 0; i < 8; ++i)
#pragma unroll
                for (int jj = 0; jj < 4; ++jj) acc[i][jj] += av[i] * pv[jj];
        }
        __syncthreads();
    }

#pragma unroll
    for (int i = 0; i < 8; ++i) {
        int b = b0 + ((i < 4) ? (ty * 4 + i) : (32 + ty * 4 + i - 4));
        *(float4*)&g_part[(size_t)cc * (B * M) + b * M + tx * 4] =
            make_float4(acc[i][0], acc[i][1], acc[i][2], acc[i][3]);
    }
}

// ---------------- FISTA update: reduce partials, prox, momentum ------------
__global__ void fista_update_kernel(float mom) {
    int i = blockIdx.x * blockDim.x + threadIdx.x;
    if (i >= B * M) return;
    float s = 0.f;
#pragma unroll
    for (int cc = 0; cc < GCH; ++cc) s += g_part[cc * (B * M) + i];
    float yv = g_y[i], cold = g_c[i];
    float x = yv - FISTA_LR * s;
    float ax = fabsf(x) - SOFT_THR;
    float cnew = (ax > 0.f) ? copysignf(ax, x) : 0.f;
    g_c[i] = cnew;
    g_y[i] = cnew + mom * (cnew - cold);
}

// ---------------- final forward: out = expm(T(c)) z0 ------------------------
__global__ void __launch_bounds__(64) final_fwd_kernel(const float* __restrict__ z0g,
                                                       float* __restrict__ out) {
    int bk = blockIdx.x;
    int b = bk >> 3, k = bk & 7;
    int t = threadIdx.x;

    __shared__ float Ts[64][65];
    __shared__ float w[64];

    const float* __restrict__ Tg = g_T + (size_t)bk * NN;
#pragma unroll
    for (int i = 0; i < 64; ++i) Ts[i][t] = Tg[i * 64 + t];
    __syncthreads();
    float Trow[64];
#pragma unroll
    for (int v = 0; v < 64; ++v) Trow[v] = Ts[t][v];

    float z = z0g[b * D + k * N + t];
    w[t] = z;
    __syncthreads();

    float acc = z;
#pragma unroll
    for (int l = 1; l <= LFF; ++l) {
        float s0 = 0.f, s1 = 0.f, s2 = 0.f, s3 = 0.f;
        const float4* wp = (const float4*)w;
#pragma unroll
        for (int v = 0; v < 16; ++v) {
            float4 w4 = wp[v];
            s0 += Trow[4 * v + 0] * w4.x;
            s1 += Trow[4 * v + 1] * w4.y;
            s2 += Trow[4 * v + 2] * w4.z;
            s3 += Trow[4 * v + 3] * w4.w;
        }
        float s = (s0 + s1) + (s2 + s3);
        __syncthreads();
        w[t] = s;
        acc += c_invf[l] * s;
        __syncthreads();
    }
    out[b * D + k * N + t] = acc;
}

// ---------------- host driver ----------------------------------------------
extern "C" void kernel_launch(void* const* d_in, const int* in_sizes, int n_in,
                              void* d_out, int out_size) {
    const float* z0  = (const float*)d_in[0];   // feature_0 [B, D]
    const float* z1  = (const float*)d_in[1];   // feature_1 [B, D]
    const float* psi = (const float*)d_in[2];   // psi [K, M, N, N]
    float* out = (float*)d_out;                 // [B, D] fp32

    cudaFuncSetAttribute(gemm_T_kernel,
                         cudaFuncAttributeMaxDynamicSharedMemorySize,
                         SMEM_T_BYTES);

    init_kernel<<<(B * M + 255) / 256, 256>>>();

    float t = 1.0f;
    for (int it = 0; it < FISTA_ITERS; ++it) {
        gemm_T_kernel<<<dim3(32, 2, KB), 256, SMEM_T_BYTES>>>(psi, 0);
        expm_grad_kernel<<<B * KB, 64>>>(z0, z1);
        gemm_g_kernel<<<dim3(GCH, 4), 128>>>(psi);
        float tn = 0.5f * (1.0f + sqrtf(1.0f + 4.0f * t * t));
        float mom = (t - 1.0f) / tn;
        t = tn;
        fista_update_kernel<<<(B * M + 255) / 256, 256>>>(mom);
    }

    gemm_T_kernel<<<dim3(32, 2, KB), 256, SMEM_T_BYTES>>>(psi, 1);
    final_fwd_kernel<<<B * KB, 64>>>(z0, out);
}

// round 8
// speedup vs baseline: 1.6684x; 1.1542x over previous
#include <cuda_runtime.h>
#include <math.h>

// Problem constants
#define B   256
#define D   512
#define KB  8         // number of block-diagonal blocks
#define M   64        // dictionary size
#define N   64        // block dim
#define NN  4096      // N*N
#define FISTA_ITERS 20
#define FISTA_LR    0.01f
#define LAMBDA_PRIOR 0.05f
#define SOFT_THR    (FISTA_LR * LAMBDA_PRIOR)
#define LFI 9         // forward Taylor terms inside FISTA loop
#define JGR 7         // gradient pair cutoff: i+l <= JGR
#define LFF 12        // final forward Taylor terms
#define GCH 128       // split-K chunks for the gradient GEMM (chunk length 256)

#define SMEM_T_BYTES (2 * 64 * 132 * 4)   // 67584 dynamic smem for gemm_T

typedef unsigned long long ull;
// packed fp32x2 helpers (Blackwell sm_103a)
#define FMA2(acc, a, b) asm("fma.rn.f32x2 %0, %1, %2, %0;" : "+l"(acc) : "l"(a), "l"(b))
#define PK2(d, lo, hi)  asm("mov.b64 %0, {%1, %2};" : "=l"(d) : "f"(lo), "f"(hi))
#define UPK2(lo, hi, s) asm("mov.b64 {%0, %1}, %2;" : "=f"(lo), "=f"(hi) : "l"(s))

// ---------------- scratch (static device globals; no allocation) -----------
__device__ float g_T[B * KB * NN];        // 32 MB
__device__ float g_dLdT[B * KB * NN];     // 32 MB
__device__ float g_psiT[KB * NN * M];     // 8 MB: psiT[k][uv][m]
__device__ float g_c[B * M];
__device__ float g_y[B * M];
__device__ float g_cT[M * B];             // transposed coef [m][b]
__device__ float g_yT[M * B];
__device__ float g_part[GCH * B * M];     // 8 MB partial gradients

__constant__ float c_invf[16] = {
    1.0f, 1.0f, 0.5f,
    1.6666666666666666e-1f, 4.1666666666666664e-2f, 8.3333333333333332e-3f,
    1.3888888888888889e-3f, 1.9841269841269841e-4f, 2.4801587301587302e-5f,
    2.7557319223985893e-6f, 2.7557319223985888e-7f, 2.5052108385441720e-8f,
    2.0876756987868100e-9f, 1.6059043836821613e-10f, 1.1470745597729725e-11f,
    7.6471637318198164e-13f};

// ---------------- init: zero c, y, yT ---------------------------------------
__global__ void init_kernel() {
    int i = blockIdx.x * blockDim.x + threadIdx.x;
    if (i < B * M) { g_c[i] = 0.0f; g_y[i] = 0.0f; g_yT[i] = 0.0f; }
}

// ---------------- one-time: psiT[k][uv][m] = psi[k][m][uv] ------------------
__global__ void transpose_psi_kernel(const float* __restrict__ psi) {
    __shared__ float tile[32][33];
    int k = blockIdx.z;
    int uv0 = blockIdx.x * 32, m0 = blockIdx.y * 32;
    int tx = threadIdx.x, ty = threadIdx.y;
#pragma unroll
    for (int i = ty; i < 32; i += 8)
        tile[i][tx] = psi[((size_t)k * M + m0 + i) * NN + uv0 + tx];
    __syncthreads();
#pragma unroll
    for (int i = ty; i < 32; i += 8)
        g_psiT[((size_t)k * NN + uv0 + i) * M + m0 + tx] = tile[tx][i];
}

// ---------------- T = coef @ psi  (per k: [B,M] @ [M,NN]) -------------------
// 128x128 output tile, K=64. 256 threads, 8x8 per thread, f32x2 packed math.
// grid (NN/128=32, B/128=2, KB). Reads transposed coef (g_yT / g_cT).
__global__ void __launch_bounds__(256) gemm_T_kernel(const float* __restrict__ psi,
                                                     int use_c) {
    const float* __restrict__ coefT = use_c ? g_cT : g_yT;   // [M][B]
    extern __shared__ float sm[];
    float (*Ys)[132] = (float(*)[132])sm;              // [m][b]
    float (*Ps)[132] = (float(*)[132])(sm + 64 * 132); // [m][col]

    int ct = blockIdx.x, bt = blockIdx.y, k = blockIdx.z;
    int tid = threadIdx.x;
    int tx = tid & 15, ty = tid >> 4;
    int col0 = ct * 128, b0 = bt * 128;

    // Ys: 64m x 128b, direct float4 copies from coefT
#pragma unroll
    for (int it = 0; it < 8; ++it) {
        int idx = it * 256 + tid;       // 2048 float4
        int b4 = idx & 31, m = idx >> 5;
        *(float4*)&Ys[m][b4 * 4] = *(const float4*)&coefT[m * B + b0 + b4 * 4];
    }
    // Ps: 64m x 128c
#pragma unroll
    for (int it = 0; it < 8; ++it) {
        int idx = it * 256 + tid;
        int c4 = idx & 31, m = idx >> 5;
        *(float4*)&Ps[m][c4 * 4] =
            *(const float4*)&psi[((size_t)k * M + m) * NN + col0 + c4 * 4];
    }
    __syncthreads();

    ull acc[8][4];
#pragma unroll
    for (int i = 0; i < 8; ++i)
#pragma unroll
        for (int j = 0; j < 4; ++j) acc[i][j] = 0ull;

#pragma unroll 2
    for (int m = 0; m < 64; ++m) {
        float4 a0 = *(const float4*)&Ys[m][ty * 4];
        float4 a1 = *(const float4*)&Ys[m][64 + ty * 4];
        float4 p0 = *(const float4*)&Ps[m][tx * 4];
        float4 p1 = *(const float4*)&Ps[m][64 + tx * 4];
        ull ad[8], pp[4];
        PK2(ad[0], a0.x, a0.x); PK2(ad[1], a0.y, a0.y);
        PK2(ad[2], a0.z, a0.z); PK2(ad[3], a0.w, a0.w);
        PK2(ad[4], a1.x, a1.x); PK2(ad[5], a1.y, a1.y);
        PK2(ad[6], a1.z, a1.z); PK2(ad[7], a1.w, a1.w);
        PK2(pp[0], p0.x, p0.y); PK2(pp[1], p0.z, p0.w);
        PK2(pp[2], p1.x, p1.y); PK2(pp[3], p1.z, p1.w);
#pragma unroll
        for (int i = 0; i < 8; ++i)
#pragma unroll
            for (int j = 0; j < 4; ++j) FMA2(acc[i][j], ad[i], pp[j]);
    }

#pragma unroll
    for (int i = 0; i < 8; ++i) {
        int b = b0 + ((i < 4) ? (ty * 4 + i) : (64 + ty * 4 + i - 4));
        float c0, c1, c2, c3, c4, c5, c6, c7;
        UPK2(c0, c1, acc[i][0]); UPK2(c2, c3, acc[i][1]);
        UPK2(c4, c5, acc[i][2]); UPK2(c6, c7, acc[i][3]);
        float* orow = &g_T[((size_t)b * KB + k) * NN + col0];
        *(float4*)&orow[tx * 4]      = make_float4(c0, c1, c2, c3);
        *(float4*)&orow[64 + tx * 4] = make_float4(c4, c5, c6, c7);
    }
}

// ---------------- per-(b,k): forward series + rank-factored expm VJP --------
__global__ void __launch_bounds__(64) expm_grad_kernel(const float* __restrict__ z0g,
                                                       const float* __restrict__ z1g) {
    int bk = blockIdx.x, b = bk >> 3, k = bk & 7, t = threadIdx.x;
    __shared__ float Ts[64][65];
    __shared__ float qs[LFI + 1][64];
    __shared__ float pex[2][64];
    __shared__ float pst[64][8];

    const float* __restrict__ Tg = g_T + (size_t)bk * NN;
#pragma unroll
    for (int i = 0; i < 64; ++i) Ts[i][t] = Tg[i * 64 + t];
    __syncthreads();

    float Trow[64], Tcol[64];
#pragma unroll
    for (int v = 0; v < 64; ++v) Trow[v] = Ts[t][v];
#pragma unroll
    for (int w = 0; w < 64; ++w) Tcol[w] = Ts[w][t];

    float z0v = z0g[b * D + k * N + t];
    qs[0][t] = z0v;
    __syncthreads();

    float ql[JGR + 1];
    ql[0] = z0v;
    float fwd = z0v;
#pragma unroll
    for (int l = 1; l <= LFI; ++l) {
        float s0 = 0.f, s1 = 0.f, s2 = 0.f, s3 = 0.f;
        const float4* qp = (const float4*)qs[l - 1];
#pragma unroll
        for (int v = 0; v < 16; ++v) {
            float4 q4 = qp[v];
            s0 += Trow[4 * v + 0] * q4.x;
            s1 += Trow[4 * v + 1] * q4.y;
            s2 += Trow[4 * v + 2] * q4.z;
            s3 += Trow[4 * v + 3] * q4.w;
        }
        float s = (s0 + s1) + (s2 + s3);
        qs[l][t] = s;
        if (l <= JGR) ql[l] = s;
        fwd += c_invf[l] * s;
        __syncthreads();
    }

    float r = fwd - z1g[b * D + k * N + t];
    pex[0][t] = r;
    pst[t][0] = r;
    __syncthreads();
#pragma unroll
    for (int i = 1; i <= JGR; ++i) {
        float s0 = 0.f, s1 = 0.f, s2 = 0.f, s3 = 0.f;
        const float4* pp = (const float4*)pex[(i - 1) & 1];
#pragma unroll
        for (int w = 0; w < 16; ++w) {
            float4 p4 = pp[w];
            s0 += Tcol[4 * w + 0] * p4.x;
            s1 += Tcol[4 * w + 1] * p4.y;
            s2 += Tcol[4 * w + 2] * p4.z;
            s3 += Tcol[4 * w + 3] * p4.w;
        }
        float s = (s0 + s1) + (s2 + s3);
        pex[i & 1][t] = s;
        pst[t][i] = s;
        __syncthreads();
    }

    float wv[JGR + 1];
#pragma unroll
    for (int i = 0; i <= JGR; ++i) {
        float s = 0.f;
#pragma unroll
        for (int l = 0; l + i <= JGR; ++l) s += c_invf[i + l + 1] * ql[l];
        wv[i] = s;
    }

    float* __restrict__ outg = g_dLdT + (size_t)bk * NN;
#pragma unroll 4
    for (int u = 0; u < 64; ++u) {
        float4 pa = *(const float4*)&pst[u][0];
        float4 pb = *(const float4*)&pst[u][4];
        float s = pa.x * wv[0] + pa.y * wv[1] + pa.z * wv[2] + pa.w * wv[3]
                + pb.x * wv[4] + pb.y * wv[5] + pb.z * wv[6] + pb.w * wv[7];
        outg[u * 64 + t] = s;
    }
}

// ---------------- g[b,m] = sum_{k,uv} dLdT[b,k,uv] psiT[k,uv,m]  (split-K) --
// grid (GCH=128 chunks of 256, 4 btiles), 128 threads, 64b x 64m tile.
// As staged [j][b] with column-rotation swizzle via register 4x4 transpose;
// Pm staged directly from psiT. Inner loop f32x2-packed along b.
__global__ void __launch_bounds__(128) gemm_g_kernel() {
    int cc = blockIdx.x, bt = blockIdx.y;
    int k = cc >> 4;
    int win = (cc & 15) * 256;
    int b0 = bt * 64;
    int tid = threadIdx.x;
    int tx = tid & 15, ty = tid >> 4;   // tx: m-group of 4, ty in [0,8): b groups

    __shared__ float As[64][68];   // [j][b phys], phys col = (b + 4*(j>>2)) & 63
    __shared__ float Pm[64][68];   // [j][m]

    ull acc[4][4];                 // [bpair][m]; pairs: rows (4ty,4ty+1),(4ty+2,4ty+3),
#pragma unroll                     //                     (32+4ty,+1),(32+4ty+2,+3)
    for (int i = 0; i < 4; ++i)
#pragma unroll
        for (int j = 0; j < 4; ++j) acc[i][j] = 0ull;

    for (int step = 0; step < 4; ++step) {
        int j0 = win + step * 64;
        // As staging: register 4x4 transpose, swizzled conflict-free STS.128
#pragma unroll
        for (int it = 0; it < 2; ++it) {
            int blk = it * 128 + tid;
            int jb = blk & 15, bb = blk >> 4;
            const float* base = &g_dLdT[((size_t)(b0 + bb * 4) * KB + k) * NN + j0 + jb * 4];
            float4 v0 = *(const float4*)(base);
            float4 v1 = *(const float4*)(base + (size_t)KB * NN);
            float4 v2 = *(const float4*)(base + (size_t)2 * KB * NN);
            float4 v3 = *(const float4*)(base + (size_t)3 * KB * NN);
            int ca = (bb * 4 + jb * 4) & 63;
            *(float4*)&As[jb * 4 + 0][ca] = make_float4(v0.x, v1.x, v2.x, v3.x);
            *(float4*)&As[jb * 4 + 1][ca] = make_float4(v0.y, v1.y, v2.y, v3.y);
            *(float4*)&As[jb * 4 + 2][ca] = make_float4(v0.z, v1.z, v2.z, v3.z);
            *(float4*)&As[jb * 4 + 3][ca] = make_float4(v0.w, v1.w, v2.w, v3.w);
        }
        // Pm staging: direct float4 copy from psiT
#pragma unroll
        for (int it = 0; it < 8; ++it) {
            int idx = it * 128 + tid;
            int m4 = idx & 15, j = idx >> 4;
            *(float4*)&Pm[j][m4 * 4] =
                *(const float4*)&g_psiT[((size_t)k * NN + j0 + j) * M + m4 * 4];
        }
        __syncthreads();

#pragma unroll 4
        for (int j4 = 0; j4 < 16; ++j4) {
            int rot = j4 * 4;
            int ca = (ty * 4 + rot) & 63;
            int cb = (ty * 4 + 32 + rot) & 63;
#pragma unroll
            for (int c = 0; c < 4; ++c) {
                int j = j4 * 4 + c;
                float4 A0 = *(const float4*)&As[j][ca];
                float4 A1 = *(const float4*)&As[j][cb];
                float4 P  = *(const float4*)&Pm[j][tx * 4];
                ull a00, a01, a10, a11, pd0, pd1, pd2, pd3;
                PK2(a00, A0.x, A0.y); PK2(a01, A0.z, A0.w);
                PK2(a10, A1.x, A1.y); PK2(a11, A1.z, A1.w);
                PK2(pd0, P.x, P.x); PK2(pd1, P.y, P.y);
                PK2(pd2, P.z, P.z); PK2(pd3, P.w, P.w);
                FMA2(acc[0][0], a00, pd0); FMA2(acc[0][1], a00, pd1);
                FMA2(acc[0][2], a00, pd2); FMA2(acc[0][3], a00, pd3);
                FMA2(acc[1][0], a01, pd0); FMA2(acc[1][1], a01, pd1);
                FMA2(acc[1][2], a01, pd2); FMA2(acc[1][3], a01, pd3);
                FMA2(acc[2][0], a10, pd0); FMA2(acc[2][1], a10, pd1);
                FMA2(acc[2][2], a10, pd2); FMA2(acc[2][3], a10, pd3);
                FMA2(acc[3][0], a11, pd0); FMA2(acc[3][1], a11, pd1);
                FMA2(acc[3][2], a11, pd2); FMA2(acc[3][3], a11, pd3);
            }
        }
        __syncthreads();
    }

#pragma unroll
    for (int pr = 0; pr < 4; ++pr) {
        int r0 = (pr < 2) ? (ty * 4 + 2 * pr) : (32 + ty * 4 + 2 * (pr - 2));
        float x0, x1, y0, y1, z0, z1, w0, w1;
        UPK2(x0, x1, acc[pr][0]); UPK2(y0, y1, acc[pr][1]);
        UPK2(z0, z1, acc[pr][2]); UPK2(w0, w1, acc[pr][3]);
        *(float4*)&g_part[(size_t)cc * (B * M) + (b0 + r0) * M + tx * 4] =
            make_float4(x0, y0, z0, w0);
        *(float4*)&g_part[(size_t)cc * (B * M) + (b0 + r0 + 1) * M + tx * 4] =
            make_float4(x1, y1, z1, w1);
    }
}

// ---------------- FISTA update: reduce partials, prox, momentum, write T ----
__global__ void fista_update_kernel(float mom) {
    int i4 = blockIdx.x * blockDim.x + threadIdx.x;
    if (i4 >= (B * M) / 4) return;
    int i = i4 * 4;
    float4 s = make_float4(0.f, 0.f, 0.f, 0.f);
#pragma unroll 8
    for (int cc = 0; cc < GCH; ++cc) {
        float4 p = *(const float4*)&g_part[(size_t)cc * (B * M) + i];
        s.x += p.x; s.y += p.y; s.z += p.z; s.w += p.w;
    }
    float4 yv = *(const float4*)&g_y[i];
    float4 co = *(const float4*)&g_c[i];
    float g[4] = {s.x, s.y, s.z, s.w};
    float yy[4] = {yv.x, yv.y, yv.z, yv.w};
    float cc_[4] = {co.x, co.y, co.z, co.w};
    float cn[4], yn[4];
#pragma unroll
    for (int r = 0; r < 4; ++r) {
        float x = yy[r] - FISTA_LR * g[r];
        float ax = fabsf(x) - SOFT_THR;
        cn[r] = (ax > 0.f) ? copysignf(ax, x) : 0.f;
        yn[r] = cn[r] + mom * (cn[r] - cc_[r]);
    }
    *(float4*)&g_c[i] = make_float4(cn[0], cn[1], cn[2], cn[3]);
    *(float4*)&g_y[i] = make_float4(yn[0], yn[1], yn[2], yn[3]);
    int b = i >> 6, m = i & 63;
#pragma unroll
    for (int r = 0; r < 4; ++r) {
        g_cT[(m + r) * B + b] = cn[r];
        g_yT[(m + r) * B + b] = yn[r];
    }
}

// ---------------- final forward: out = expm(T(c)) z0 ------------------------
__global__ void __launch_bounds__(64) final_fwd_kernel(const float* __restrict__ z0g,
                                                       float* __restrict__ out) {
    int bk = blockIdx.x;
    int b = bk >> 3, k = bk & 7;
    int t = threadIdx.x;

    __shared__ float Ts[64][65];
    __shared__ float w[64];

    const float* __restrict__ Tg = g_T + (size_t)bk * NN;
#pragma unroll
    for (int i = 0; i < 64; ++i) Ts[i][t] = Tg[i * 64 + t];
    __syncthreads();
    float Trow[64];
#pragma unroll
    for (int v = 0; v < 64; ++v) Trow[v] = Ts[t][v];

    float z = z0g[b * D + k * N + t];
    w[t] = z;
    __syncthreads();

    float acc = z;
#pragma unroll
    for (int l = 1; l <= LFF; ++l) {
        float s0 = 0.f, s1 = 0.f, s2 = 0.f, s3 = 0.f;
        const float4* wp = (const float4*)w;
#pragma unroll
        for (int v = 0; v < 16; ++v) {
            float4 w4 = wp[v];
            s0 += Trow[4 * v + 0] * w4.x;
            s1 += Trow[4 * v + 1] * w4.y;
            s2 += Trow[4 * v + 2] * w4.z;
            s3 += Trow[4 * v + 3] * w4.w;
        }
        float s = (s0 + s1) + (s2 + s3);
        __syncthreads();
        w[t] = s;
        acc += c_invf[l] * s;
        __syncthreads();
    }
    out[b * D + k * N + t] = acc;
}

// ---------------- host driver ----------------------------------------------
extern "C" void kernel_launch(void* const* d_in, const int* in_sizes, int n_in,
                              void* d_out, int out_size) {
    (void)in_sizes; (void)n_in; (void)out_size;
    const float* z0  = (const float*)d_in[0];   // feature_0 [B, D]
    const float* z1  = (const float*)d_in[1];   // feature_1 [B, D]
    const float* psi = (const float*)d_in[2];   // psi [K, M, N, N]
    float* out = (float*)d_out;                 // [B, D] fp32

    cudaFuncSetAttribute(gemm_T_kernel,
                         cudaFuncAttributeMaxDynamicSharedMemorySize,
                         SMEM_T_BYTES);

    init_kernel<<<(B * M + 255) / 256, 256>>>();
    transpose_psi_kernel<<<dim3(NN / 32, M / 32, KB), dim3(32, 8)>>>(psi);

    float t = 1.0f;
    for (int it = 0; it < FISTA_ITERS; ++it) {
        gemm_T_kernel<<<dim3(32, 2, KB), 256, SMEM_T_BYTES>>>(psi, 0);
        expm_grad_kernel<<<B * KB, 64>>>(z0, z1);
        gemm_g_kernel<<<dim3(GCH, 4), 128>>>();
        float tn = 0.5f * (1.0f + sqrtf(1.0f + 4.0f * t * t));
        float mom = (t - 1.0f) / tn;
        t = tn;
        fista_update_kernel<<<((B * M) / 4 + 255) / 256, 256>>>(mom);
    }

    gemm_T_kernel<<<dim3(32, 2, KB), 256, SMEM_T_BYTES>>>(psi, 1);
    final_fwd_kernel<<<B * KB, 64>>>(z0, out);
}

// round 11
// speedup vs baseline: 1.7035x; 1.0211x over previous
#include <cuda_runtime.h>
#include <math.h>

// Problem constants
#define B   256
#define D   512
#define KB  8         // number of block-diagonal blocks
#define M   64        // dictionary size
#define N   64        // block dim
#define NN  4096      // N*N
#define FISTA_ITERS 20
#define FISTA_LR    0.01f
#define LAMBDA_PRIOR 0.05f
#define SOFT_THR    (FISTA_LR * LAMBDA_PRIOR)
#define LFI 9         // forward Taylor terms inside FISTA loop
#define JGR 7         // gradient pair cutoff: i+l <= JGR
#define LFF 12        // final forward Taylor terms
#define GCH 128       // split-K chunks for the gradient GEMM (chunk length 256)

#define SMEM_T_BYTES (2 * 64 * 132 * 4)   // 67584 dynamic smem for gemm_T

typedef unsigned long long ull;
// packed fp32x2 helpers (Blackwell sm_103a)
#define FMA2(acc, a, b) asm("fma.rn.f32x2 %0, %1, %2, %0;" : "+l"(acc) : "l"(a), "l"(b))
#define PK2(d, lo, hi)  asm("mov.b64 %0, {%1, %2};" : "=l"(d) : "f"(lo), "f"(hi))
#define UPK2(lo, hi, s) asm("mov.b64 {%0, %1}, %2;" : "=f"(lo), "=f"(hi) : "l"(s))

// ---------------- scratch (static device globals; no allocation) -----------
// g_T doubles as dLdT storage: expm_grad reads its T slab fully into smem,
// then overwrites the same slab with dLdT (in-place). gemm_T regenerates T
// from scratch every iteration, so the overwrite is safe and deterministic.
__device__ float g_T[B * KB * NN];        // 32 MB
__device__ float g_psiT[KB * NN * M];     // 8 MB: psiT[k][uv][m]
__device__ float g_c[B * M];
__device__ float g_y[B * M];
__device__ float g_cT[M * B];             // transposed coef [m][b]
__device__ float g_yT[M * B];
__device__ float g_part[GCH * B * M];     // 8 MB partial gradients

__constant__ float c_invf[16] = {
    1.0f, 1.0f, 0.5f,
    1.6666666666666666e-1f, 4.1666666666666664e-2f, 8.3333333333333332e-3f,
    1.3888888888888889e-3f, 1.9841269841269841e-4f, 2.4801587301587302e-5f,
    2.7557319223985893e-6f, 2.7557319223985888e-7f, 2.5052108385441720e-8f,
    2.0876756987868100e-9f, 1.6059043836821613e-10f, 1.1470745597729725e-11f,
    7.6471637318198164e-13f};

// ---------------- init: zero c, y, yT ---------------------------------------
__global__ void init_kernel() {
    int i = blockIdx.x * blockDim.x + threadIdx.x;
    if (i < B * M) { g_c[i] = 0.0f; g_y[i] = 0.0f; g_yT[i] = 0.0f; }
}

// ---------------- one-time: psiT[k][uv][m] = psi[k][m][uv] ------------------
__global__ void transpose_psi_kernel(const float* __restrict__ psi) {
    __shared__ float tile[32][33];
    int k = blockIdx.z;
    int uv0 = blockIdx.x * 32, m0 = blockIdx.y * 32;
    int tx = threadIdx.x, ty = threadIdx.y;
#pragma unroll
    for (int i = ty; i < 32; i += 8)
        tile[i][tx] = psi[((size_t)k * M + m0 + i) * NN + uv0 + tx];
    __syncthreads();
#pragma unroll
    for (int i = ty; i < 32; i += 8)
        g_psiT[((size_t)k * NN + uv0 + i) * M + m0 + tx] = tile[tx][i];
}

// ---------------- T = coef @ psi  (per k: [B,M] @ [M,NN]) -------------------
// 128x128 output tile, K=64. 256 threads, 8x8 per thread, f32x2 packed math.
__global__ void __launch_bounds__(256) gemm_T_kernel(const float* __restrict__ psi,
                                                     int use_c) {
    const float* __restrict__ coefT = use_c ? g_cT : g_yT;   // [M][B]
    extern __shared__ float sm[];
    float (*Ys)[132] = (float(*)[132])sm;              // [m][b]
    float (*Ps)[132] = (float(*)[132])(sm + 64 * 132); // [m][col]

    int ct = blockIdx.x, bt = blockIdx.y, k = blockIdx.z;
    int tid = threadIdx.x;
    int tx = tid & 15, ty = tid >> 4;
    int col0 = ct * 128, b0 = bt * 128;

#pragma unroll
    for (int it = 0; it < 8; ++it) {
        int idx = it * 256 + tid;       // 2048 float4
        int b4 = idx & 31, m = idx >> 5;
        *(float4*)&Ys[m][b4 * 4] = *(const float4*)&coefT[m * B + b0 + b4 * 4];
    }
#pragma unroll
    for (int it = 0; it < 8; ++it) {
        int idx = it * 256 + tid;
        int c4 = idx & 31, m = idx >> 5;
        *(float4*)&Ps[m][c4 * 4] =
            *(const float4*)&psi[((size_t)k * M + m) * NN + col0 + c4 * 4];
    }
    __syncthreads();

    ull acc[8][4];
#pragma unroll
    for (int i = 0; i < 8; ++i)
#pragma unroll
        for (int j = 0; j < 4; ++j) acc[i][j] = 0ull;

#pragma unroll 2
    for (int m = 0; m < 64; ++m) {
        float4 a0 = *(const float4*)&Ys[m][ty * 4];
        float4 a1 = *(const float4*)&Ys[m][64 + ty * 4];
        float4 p0 = *(const float4*)&Ps[m][tx * 4];
        float4 p1 = *(const float4*)&Ps[m][64 + tx * 4];
        ull ad[8], pp[4];
        PK2(ad[0], a0.x, a0.x); PK2(ad[1], a0.y, a0.y);
        PK2(ad[2], a0.z, a0.z); PK2(ad[3], a0.w, a0.w);
        PK2(ad[4], a1.x, a1.x); PK2(ad[5], a1.y, a1.y);
        PK2(ad[6], a1.z, a1.z); PK2(ad[7], a1.w, a1.w);
        PK2(pp[0], p0.x, p0.y); PK2(pp[1], p0.z, p0.w);
        PK2(pp[2], p1.x, p1.y); PK2(pp[3], p1.z, p1.w);
#pragma unroll
        for (int i = 0; i < 8; ++i)
#pragma unroll
            for (int j = 0; j < 4; ++j) FMA2(acc[i][j], ad[i], pp[j]);
    }

#pragma unroll
    for (int i = 0; i < 8; ++i) {
        int b = b0 + ((i < 4) ? (ty * 4 + i) : (64 + ty * 4 + i - 4));
        float c0, c1, c2, c3, c4, c5, c6, c7;
        UPK2(c0, c1, acc[i][0]); UPK2(c2, c3, acc[i][1]);
        UPK2(c4, c5, acc[i][2]); UPK2(c6, c7, acc[i][3]);
        float* orow = &g_T[((size_t)b * KB + k) * NN + col0];
        *(float4*)&orow[tx * 4]      = make_float4(c0, c1, c2, c3);
        *(float4*)&orow[64 + tx * 4] = make_float4(c4, c5, c6, c7);
    }
}

// ---------------- per-(b,k): forward series + rank-factored expm VJP --------
// Reads T slab fully into smem, then writes dLdT IN PLACE over the same slab.
__global__ void __launch_bounds__(64) expm_grad_kernel(const float* __restrict__ z0g,
                                                       const float* __restrict__ z1g) {
    int bk = blockIdx.x, b = bk >> 3, k = bk & 7, t = threadIdx.x;
    __shared__ float Ts[64][65];
    __shared__ float qs[LFI + 1][64];
    __shared__ float pex[2][64];
    __shared__ float pst[64][8];

    float* __restrict__ Tg = g_T + (size_t)bk * NN;
#pragma unroll
    for (int i = 0; i < 64; ++i) Ts[i][t] = Tg[i * 64 + t];
    __syncthreads();

    float Trow[64], Tcol[64];
#pragma unroll
    for (int v = 0; v < 64; ++v) Trow[v] = Ts[t][v];
#pragma unroll
    for (int w = 0; w < 64; ++w) Tcol[w] = Ts[w][t];

    float z0v = z0g[b * D + k * N + t];
    qs[0][t] = z0v;
    __syncthreads();

    float ql[JGR + 1];
    ql[0] = z0v;
    float fwd = z0v;
#pragma unroll
    for (int l = 1; l <= LFI; ++l) {
        float s0 = 0.f, s1 = 0.f, s2 = 0.f, s3 = 0.f;
        const float4* qp = (const float4*)qs[l - 1];
#pragma unroll
        for (int v = 0; v < 16; ++v) {
            float4 q4 = qp[v];
            s0 += Trow[4 * v + 0] * q4.x;
            s1 += Trow[4 * v + 1] * q4.y;
            s2 += Trow[4 * v + 2] * q4.z;
            s3 += Trow[4 * v + 3] * q4.w;
        }
        float s = (s0 + s1) + (s2 + s3);
        qs[l][t] = s;
        if (l <= JGR) ql[l] = s;
        fwd += c_invf[l] * s;
        __syncthreads();
    }

    float r = fwd - z1g[b * D + k * N + t];
    pex[0][t] = r;
    pst[t][0] = r;
    __syncthreads();
#pragma unroll
    for (int i = 1; i <= JGR; ++i) {
        float s0 = 0.f, s1 = 0.f, s2 = 0.f, s3 = 0.f;
        const float4* pp = (const float4*)pex[(i - 1) & 1];
#pragma unroll
        for (int w = 0; w < 16; ++w) {
            float4 p4 = pp[w];
            s0 += Tcol[4 * w + 0] * p4.x;
            s1 += Tcol[4 * w + 1] * p4.y;
            s2 += Tcol[4 * w + 2] * p4.z;
            s3 += Tcol[4 * w + 3] * p4.w;
        }
        float s = (s0 + s1) + (s2 + s3);
        pex[i & 1][t] = s;
        pst[t][i] = s;
        __syncthreads();
    }

    float wv[JGR + 1];
#pragma unroll
    for (int i = 0; i <= JGR; ++i) {
        float s = 0.f;
#pragma unroll
        for (int l = 0; l + i <= JGR; ++l) s += c_invf[i + l + 1] * ql[l];
        wv[i] = s;
    }

    // in-place: overwrite the T slab with dLdT (all T reads above are smem/regs)
#pragma unroll 4
    for (int u = 0; u < 64; ++u) {
        float4 pa = *(const float4*)&pst[u][0];
        float4 pb = *(const float4*)&pst[u][4];
        float s = pa.x * wv[0] + pa.y * wv[1] + pa.z * wv[2] + pa.w * wv[3]
                + pb.x * wv[4] + pb.y * wv[5] + pb.z * wv[6] + pb.w * wv[7];
        Tg[u * 64 + t] = s;
    }
}

// ---------------- g[b,m] = sum_{k,uv} dLdT[b,k,uv] psiT[k,uv,m]  (split-K) --
// dLdT lives in g_T (in-place). grid (GCH, 4 btiles), 128 thr, 64b x 64m tile.
__global__ void __launch_bounds__(128) gemm_g_kernel() {
    int cc = blockIdx.x, bt = blockIdx.y;
    int k = cc >> 4;
    int win = (cc & 15) * 256;
    int b0 = bt * 64;
    int tid = threadIdx.x;
    int tx = tid & 15, ty = tid >> 4;   // tx: m-group of 4, ty in [0,8): b groups

    __shared__ float As[64][68];   // [j][b phys], phys col = (b + 4*(j>>2)) & 63
    __shared__ float Pm[64][68];   // [j][m]

    ull acc[4][4];
#pragma unroll
    for (int i = 0; i < 4; ++i)
#pragma unroll
        for (int j = 0; j < 4; ++j) acc[i][j] = 0ull;

    for (int step = 0; step < 4; ++step) {
        int j0 = win + step * 64;
        // As staging: register 4x4 transpose, swizzled conflict-free STS.128
#pragma unroll
        for (int it = 0; it < 2; ++it) {
            int blk = it * 128 + tid;
            int jb = blk & 15, bb = blk >> 4;
            const float* base = &g_T[((size_t)(b0 + bb * 4) * KB + k) * NN + j0 + jb * 4];
            float4 v0 = *(const float4*)(base);
            float4 v1 = *(const float4*)(base + (size_t)KB * NN);
            float4 v2 = *(const float4*)(base + (size_t)2 * KB * NN);
            float4 v3 = *(const float4*)(base + (size_t)3 * KB * NN);
            int ca = (bb * 4 + jb * 4) & 63;
            *(float4*)&As[jb * 4 + 0][ca] = make_float4(v0.x, v1.x, v2.x, v3.x);
            *(float4*)&As[jb * 4 + 1][ca] = make_float4(v0.y, v1.y, v2.y, v3.y);
            *(float4*)&As[jb * 4 + 2][ca] = make_float4(v0.z, v1.z, v2.z, v3.z);
            *(float4*)&As[jb * 4 + 3][ca] = make_float4(v0.w, v1.w, v2.w, v3.w);
        }
#pragma unroll
        for (int it = 0; it < 8; ++it) {
            int idx = it * 128 + tid;
            int m4 = idx & 15, j = idx >> 4;
            *(float4*)&Pm[j][m4 * 4] =
                *(const float4*)&g_psiT[((size_t)k * NN + j0 + j) * M + m4 * 4];
        }
        __syncthreads();

#pragma unroll 4
        for (int j4 = 0; j4 < 16; ++j4) {
            int rot = j4 * 4;
            int ca = (ty * 4 + rot) & 63;
            int cb = (ty * 4 + 32 + rot) & 63;
#pragma unroll
            for (int c = 0; c < 4; ++c) {
                int j = j4 * 4 + c;
                float4 A0 = *(const float4*)&As[j][ca];
                float4 A1 = *(const float4*)&As[j][cb];
                float4 P  = *(const float4*)&Pm[j][tx * 4];
                ull a00, a01, a10, a11, pd0, pd1, pd2, pd3;
                PK2(a00, A0.x, A0.y); PK2(a01, A0.z, A0.w);
                PK2(a10, A1.x, A1.y); PK2(a11, A1.z, A1.w);
                PK2(pd0, P.x, P.x); PK2(pd1, P.y, P.y);
                PK2(pd2, P.z, P.z); PK2(pd3, P.w, P.w);
                FMA2(acc[0][0], a00, pd0); FMA2(acc[0][1], a00, pd1);
                FMA2(acc[0][2], a00, pd2); FMA2(acc[0][3], a00, pd3);
                FMA2(acc[1][0], a01, pd0); FMA2(acc[1][1], a01, pd1);
                FMA2(acc[1][2], a01, pd2); FMA2(acc[1][3], a01, pd3);
                FMA2(acc[2][0], a10, pd0); FMA2(acc[2][1], a10, pd1);
                FMA2(acc[2][2], a10, pd2); FMA2(acc[2][3], a10, pd3);
                FMA2(acc[3][0], a11, pd0); FMA2(acc[3][1], a11, pd1);
                FMA2(acc[3][2], a11, pd2); FMA2(acc[3][3], a11, pd3);
            }
        }
        __syncthreads();
    }

#pragma unroll
    for (int pr = 0; pr < 4; ++pr) {
        int r0 = (pr < 2) ? (ty * 4 + 2 * pr) : (32 + ty * 4 + 2 * (pr - 2));
        float x0, x1, y0, y1, z0, z1, w0, w1;
        UPK2(x0, x1, acc[pr][0]); UPK2(y0, y1, acc[pr][1]);
        UPK2(z0, z1, acc[pr][2]); UPK2(w0, w1, acc[pr][3]);
        *(float4*)&g_part[(size_t)cc * (B * M) + (b0 + r0) * M + tx * 4] =
            make_float4(x0, y0, z0, w0);
        *(float4*)&g_part[(size_t)cc * (B * M) + (b0 + r0 + 1) * M + tx * 4] =
            make_float4(x1, y1, z1, w1);
    }
}

// ---------------- FISTA update: reduce partials, prox, momentum, transpose --
__global__ void fista_update_kernel(float mom) {
    int i4 = blockIdx.x * blockDim.x + threadIdx.x;
    if (i4 >= (B * M) / 4) return;
    int i = i4 * 4;
    float4 s = make_float4(0.f, 0.f, 0.f, 0.f);
#pragma unroll 8
    for (int cc = 0; cc < GCH; ++cc) {
        float4 p = *(const float4*)&g_part[(size_t)cc * (B * M) + i];
        s.x += p.x; s.y += p.y; s.z += p.z; s.w += p.w;
    }
    float4 yv = *(const float4*)&g_y[i];
    float4 co = *(const float4*)&g_c[i];
    float g[4] = {s.x, s.y, s.z, s.w};
    float yy[4] = {yv.x, yv.y, yv.z, yv.w};
    float cc_[4] = {co.x, co.y, co.z, co.w};
    float cn[4], yn[4];
#pragma unroll
    for (int r = 0; r < 4; ++r) {
        float x = yy[r] - FISTA_LR * g[r];
        float ax = fabsf(x) - SOFT_THR;
        cn[r] = (ax > 0.f) ? copysignf(ax, x) : 0.f;
        yn[r] = cn[r] + mom * (cn[r] - cc_[r]);
    }
    *(float4*)&g_c[i] = make_float4(cn[0], cn[1], cn[2], cn[3]);
    *(float4*)&g_y[i] = make_float4(yn[0], yn[1], yn[2], yn[3]);
    int b = i >> 6, m = i & 63;
#pragma unroll
    for (int r = 0; r < 4; ++r) {
        g_cT[(m + r) * B + b] = cn[r];
        g_yT[(m + r) * B + b] = yn[r];
    }
}

// ---------------- final forward: out = expm(T(c)) z0 ------------------------
__global__ void __launch_bounds__(64) final_fwd_kernel(const float* __restrict__ z0g,
                                                       float* __restrict__ out) {
    int bk = blockIdx.x;
    int b = bk >> 3, k = bk & 7;
    int t = threadIdx.x;

    __shared__ float Ts[64][65];
    __shared__ float w[64];

    const float* __restrict__ Tg = g_T + (size_t)bk * NN;
#pragma unroll
    for (int i = 0; i < 64; ++i) Ts[i][t] = Tg[i * 64 + t];
    __syncthreads();
    float Trow[64];
#pragma unroll
    for (int v = 0; v < 64; ++v) Trow[v] = Ts[t][v];

    float z = z0g[b * D + k * N + t];
    w[t] = z;
    __syncthreads();

    float acc = z;
#pragma unroll
    for (int l = 1; l <= LFF; ++l) {
        float s0 = 0.f, s1 = 0.f, s2 = 0.f, s3 = 0.f;
        const float4* wp = (const float4*)w;
#pragma unroll
        for (int v = 0; v < 16; ++v) {
            float4 w4 = wp[v];
            s0 += Trow[4 * v + 0] * w4.x;
            s1 += Trow[4 * v + 1] * w4.y;
            s2 += Trow[4 * v + 2] * w4.z;
            s3 += Trow[4 * v + 3] * w4.w;
        }
        float s = (s0 + s1) + (s2 + s3);
        __syncthreads();
        w[t] = s;
        acc += c_invf[l] * s;
        __syncthreads();
    }
    out[b * D + k * N + t] = acc;
}

// ---------------- host driver ----------------------------------------------
extern "C" void kernel_launch(void* const* d_in, const int* in_sizes, int n_in,
                              void* d_out, int out_size) {
    (void)in_sizes; (void)n_in; (void)out_size;
    const float* z0  = (const float*)d_in[0];   // feature_0 [B, D]
    const float* z1  = (const float*)d_in[1];   // feature_1 [B, D]
    const float* psi = (const float*)d_in[2];   // psi [K, M, N, N]
    float* out = (float*)d_out;                 // [B, D] fp32

    cudaFuncSetAttribute(gemm_T_kernel,
                         cudaFuncAttributeMaxDynamicSharedMemorySize,
                         SMEM_T_BYTES);

    init_kernel<<<(B * M + 255) / 256, 256>>>();
    transpose_psi_kernel<<<dim3(NN / 32, M / 32, KB), dim3(32, 8)>>>(psi);

    float t = 1.0f;
    for (int it = 0; it < FISTA_ITERS; ++it) {
        gemm_T_kernel<<<dim3(32, 2, KB), 256, SMEM_T_BYTES>>>(psi, 0);
        expm_grad_kernel<<<B * KB, 64>>>(z0, z1);
        gemm_g_kernel<<<dim3(GCH, 4), 128>>>();
        float tn = 0.5f * (1.0f + sqrtf(1.0f + 4.0f * t * t));
        float mom = (t - 1.0f) / tn;
        t = tn;
        fista_update_kernel<<<((B * M) / 4 + 255) / 256, 256>>>(mom);
    }

    gemm_T_kernel<<<dim3(32, 2, KB), 256, SMEM_T_BYTES>>>(psi, 1);
    final_fwd_kernel<<<B * KB, 64>>>(z0, out);
}